// round 8
// baseline (speedup 1.0000x reference)
#include <cuda_runtime.h>
#include <cuda_fp16.h>
#include <stdint.h>

#define NN 4096
#define THREADS 128
#define STAGES 3
#define BK 64
#define KT (NN / BK)   // 64 iterations
#define BM 128
#define BN 128
#define LDB 144  // bytes per smem row: 64 halves (128B) + 16B pad -> conflict-free ldmatrix

#define ASTG (BM * LDB)             // 18432 bytes per operand stage
#define STG (2 * ASTG)              // 36864 per stage (A+B)
#define SMEM_TOTAL (STAGES * STG)   // 110592

// Scratch (device globals: no allocations).
__device__ __half g_Sh[(size_t)NN * NN];   // f16 logits, then probs in-place (32 MB)
__device__ __half g_Fh[(size_t)NN * NN];   // f16 feats (32 MB)

__device__ __forceinline__ uint32_t smem_u32(const void* p) {
    uint32_t a;
    asm("{ .reg .u64 t; cvta.to.shared.u64 t, %1; cvt.u32.u64 %0, t; }" : "=r"(a) : "l"(p));
    return a;
}

#define CP_ASYNC16(dst, src) \
    asm volatile("cp.async.cg.shared.global [%0], [%1], 16;" :: "r"(dst), "l"(src) : "memory")
#define CP_COMMIT() asm volatile("cp.async.commit_group;" ::: "memory")
#define CP_WAIT(n) asm volatile("cp.async.wait_group %0;" ::"n"(n) : "memory")

#define LDSM_X4(r0, r1, r2, r3, addr)                                        \
    asm volatile("ldmatrix.sync.aligned.m8n8.x4.shared.b16 {%0,%1,%2,%3}, [%4];" \
                 : "=r"(r0), "=r"(r1), "=r"(r2), "=r"(r3) : "r"(addr))

#define MMA_F16(d, a, b0, b1)                                                \
    asm volatile(                                                            \
        "mma.sync.aligned.m16n8k16.row.col.f32.f16.f16.f32 "                 \
        "{%0,%1,%2,%3}, {%4,%5,%6,%7}, {%8,%9}, {%0,%1,%2,%3};"              \
        : "+f"((d)[0]), "+f"((d)[1]), "+f"((d)[2]), "+f"((d)[3])             \
        : "r"((a)[0]), "r"((a)[1]), "r"((a)[2]), "r"((a)[3]),                \
          "r"(b0), "r"(b1))

// NT GEMM, f16 inputs, fp32 accum, OT output: C[i][j] = scale*sum_k A[i][k]*B[j][k]
// 4 warps, 64x64 warp tiles (2x2 grid).
template <typename OT>
__global__ __launch_bounds__(THREADS, 2) void gemm_nt_f16(const __half* __restrict__ A,
                                                          const __half* __restrict__ B,
                                                          OT* __restrict__ C, float scale) {
    extern __shared__ char smem[];
    const uint32_t sb = smem_u32(smem);
    const int tid = threadIdx.x;
    const int wid = tid >> 5;
    const int lane = tid & 31;
    const int q = lane >> 2, r = lane & 3;
    const int wm = wid & 1;   // 2 warp rows x 64
    const int wn = wid >> 1;  // 2 warp cols x 64
    const int rowBase = blockIdx.y * BM;
    const int colBase = blockIdx.x * BN;

    // cp.async: per operand tile 128 rows x 128B = 1024 chunks; 8/thread/operand
    const int ldRow = tid >> 3;          // 0..15, +16 steps
    const int ldC = (tid & 7) * 16;
    const char* Ag = (const char*)A + ((size_t)(rowBase + ldRow) * NN) * 2 + ldC;
    const char* Bg = (const char*)B + ((size_t)(colBase + ldRow) * NN) * 2 + ldC;
    const size_t GROW = (size_t)16 * NN * 2;  // 16-row stride

    // ldmatrix lane mapping
    const int ml = lane >> 3;
    const int lrow = (ml & 1) * 8 + (lane & 7);
    const int lk = (ml >> 1) * 16;
    const uint32_t aoff = (uint32_t)((wm * 64 + lrow) * LDB + lk);
    const uint32_t boff = (uint32_t)(ASTG + (wn * 64 + lrow) * LDB + lk);

    float c[4][8][4];
#pragma unroll
    for (int i = 0; i < 4; i++)
#pragma unroll
        for (int j = 0; j < 8; j++)
#pragma unroll
            for (int e = 0; e < 4; e++) c[i][j][e] = 0.f;

#define LOADK(sidx)                                                                \
    do {                                                                           \
        const uint32_t s_b = sb + (sidx) * STG;                                    \
        _Pragma("unroll") for (int l = 0; l < 8; l++) {                            \
            CP_ASYNC16(s_b + (ldRow + l * 16) * LDB + ldC, Ag + l * GROW);         \
            CP_ASYNC16(s_b + ASTG + (ldRow + l * 16) * LDB + ldC, Bg + l * GROW);  \
        }                                                                          \
        CP_COMMIT();                                                               \
        Ag += 128;                                                                 \
        Bg += 128;                                                                 \
    } while (0)

    LOADK(0);
    LOADK(1);

    int scur = 0;
    int sld = 2;

#define LOAD_FRAGS(buf, base_a, base_b, ks)                                        \
    do {                                                                           \
        _Pragma("unroll") for (int im = 0; im < 4; im++)                           \
            LDSM_X4(a[buf][im][0], a[buf][im][1], a[buf][im][2], a[buf][im][3],    \
                    (base_a) + im * (16 * LDB) + (ks) * 32);                       \
        _Pragma("unroll") for (int jn = 0; jn < 4; jn++)                           \
            LDSM_X4(b[buf][jn][0], b[buf][jn][1], b[buf][jn][2], b[buf][jn][3],    \
                    (base_b) + jn * (16 * LDB) + (ks) * 32);                       \
    } while (0)

    for (int kt = 0; kt < KT; kt++) {
        CP_WAIT(1);
        __syncthreads();  // stage (kt-1)%3 reads complete -> reusable
        if (kt + 2 < KT) {
            LOADK(sld);
            sld = (sld == STAGES - 1) ? 0 : sld + 1;
        } else {
            CP_COMMIT();
        }

        const uint32_t abase = sb + scur * STG + aoff;
        const uint32_t bbase = sb + scur * STG + boff;
        scur = (scur == STAGES - 1) ? 0 : scur + 1;

        uint32_t a[2][4][4], b[2][4][4];
        LOAD_FRAGS(0, abase, bbase, 0);
#pragma unroll
        for (int ks = 0; ks < 4; ks++) {
            const int cur = ks & 1;
            if (ks < 3) LOAD_FRAGS(cur ^ 1, abase, bbase, ks + 1);
#pragma unroll
            for (int im = 0; im < 4; im++)
#pragma unroll
                for (int jn = 0; jn < 4; jn++) {
                    MMA_F16(c[im][2 * jn + 0], a[cur][im], b[cur][jn][0], b[cur][jn][2]);
                    MMA_F16(c[im][2 * jn + 1], a[cur][im], b[cur][jn][1], b[cur][jn][3]);
                }
        }
    }

    // epilogue
#pragma unroll
    for (int im = 0; im < 4; im++) {
        const int row0 = rowBase + wm * 64 + im * 16 + q;
#pragma unroll
        for (int n8 = 0; n8 < 8; n8++) {
            const int col = colBase + wn * 64 + n8 * 8 + 2 * r;
            if constexpr (sizeof(OT) == 4) {
                float2 v0 = make_float2(c[im][n8][0] * scale, c[im][n8][1] * scale);
                float2 v1 = make_float2(c[im][n8][2] * scale, c[im][n8][3] * scale);
                *reinterpret_cast<float2*>((float*)C + (size_t)row0 * NN + col) = v0;
                *reinterpret_cast<float2*>((float*)C + (size_t)(row0 + 8) * NN + col) = v1;
            } else {
                __half2 h0 = __floats2half2_rn(c[im][n8][0] * scale, c[im][n8][1] * scale);
                __half2 h1 = __floats2half2_rn(c[im][n8][2] * scale, c[im][n8][3] * scale);
                *reinterpret_cast<__half2*>((__half*)C + (size_t)row0 * NN + col) = h0;
                *reinterpret_cast<__half2*>((__half*)C + (size_t)(row0 + 8) * NN + col) = h1;
            }
        }
    }
}

// ---------------- prep: feats f32 -> f16 ----------------
__global__ __launch_bounds__(256) void prep_feats(const float* __restrict__ in,
                                                  __half* __restrict__ out) {
    size_t i = ((size_t)blockIdx.x * 256 + threadIdx.x) * 8;
    float4 v0 = *reinterpret_cast<const float4*>(in + i);
    float4 v1 = *reinterpret_cast<const float4*>(in + i + 4);
    __half2 h[4];
    h[0] = __floats2half2_rn(v0.x, v0.y);
    h[1] = __floats2half2_rn(v0.z, v0.w);
    h[2] = __floats2half2_rn(v1.x, v1.y);
    h[3] = __floats2half2_rn(v1.z, v1.w);
    *reinterpret_cast<uint4*>(out + i) = *reinterpret_cast<uint4*>(h);
}

// ---------------- row softmax on f16 logits, diag masked, f16 probs in-place ----------------
__global__ __launch_bounds__(256) void softmax_rows(__half* __restrict__ S) {
    __shared__ float row[NN];  // 16 KB
    __shared__ float red[256];
    const int ri = blockIdx.x;
    const int t = threadIdx.x;
    __half2* rp = reinterpret_cast<__half2*>(S + (size_t)ri * NN);

    for (int j = t; j < NN / 2; j += 256) {
        float2 v = __half22float2(rp[j]);
        row[2 * j] = v.x;
        row[2 * j + 1] = v.y;
    }
    __syncthreads();
    if (t == 0) row[ri] = -3.4e38f;  // mask diagonal
    __syncthreads();

    float m = -3.4e38f;
    for (int j = t; j < NN; j += 256) m = fmaxf(m, row[j]);
    red[t] = m;
    __syncthreads();
    for (int s = 128; s > 0; s >>= 1) {
        if (t < s) red[t] = fmaxf(red[t], red[t + s]);
        __syncthreads();
    }
    m = red[0];
    __syncthreads();

    float sum = 0.f;
    for (int j = t; j < NN; j += 256) {
        float e = __expf(row[j] - m);
        row[j] = e;
        sum += e;
    }
    red[t] = sum;
    __syncthreads();
    for (int s = 128; s > 0; s >>= 1) {
        if (t < s) red[t] += red[t + s];
        __syncthreads();
    }
    const float inv = 1.f / red[0];
    __syncthreads();

    for (int j = t; j < NN / 2; j += 256)
        rp[j] = __floats2half2_rn(row[2 * j] * inv, row[2 * j + 1] * inv);
}

extern "C" void kernel_launch(void* const* d_in, const int* in_sizes, int n_in,
                              void* d_out, int out_size) {
    const float* feats = (const float*)d_in[0];
    float* out = (float*)d_out;

    void *sp, *fp;
    cudaGetSymbolAddress(&sp, g_Sh);
    cudaGetSymbolAddress(&fp, g_Fh);
    __half* Sh = (__half*)sp;
    __half* Fh = (__half*)fp;

    cudaFuncSetAttribute(gemm_nt_f16<__half>, cudaFuncAttributeMaxDynamicSharedMemorySize,
                         SMEM_TOTAL);
    cudaFuncSetAttribute(gemm_nt_f16<float>, cudaFuncAttributeMaxDynamicSharedMemorySize,
                         SMEM_TOTAL);

    prep_feats<<<(NN * NN) / 2048, 256>>>(feats, Fh);

    dim3 grid(NN / BN, NN / BM);  // (32, 32)
    // S = Fh @ Fh^T / D  (f16 logits out)
    gemm_nt_f16<__half><<<grid, THREADS, SMEM_TOTAL>>>(Fh, Fh, Sh, 1.0f / (float)NN);
    // P = softmax(S), diag masked, in-place f16
    softmax_rows<<<NN, 256>>>(Sh);
    // out = P @ Fh^T / sqrt(D)  (fp32 out)
    gemm_nt_f16<float><<<grid, THREADS, SMEM_TOTAL>>>(Sh, Fh, out, 1.0f / 64.0f);
}

// round 10
// speedup vs baseline: 1.3272x; 1.3272x over previous
#include <cuda_runtime.h>
#include <cuda_fp16.h>
#include <stdint.h>

#define NN 4096
#define THREADS 256
#define STAGES 3
#define BK 64
#define KT (NN / BK)   // 64 iterations
#define BM 128
#define BN 128
#define LDB 144  // bytes per smem row: 64 halves (128B) + 16B pad -> conflict-free ldmatrix

#define ASTG (BM * LDB)             // 18432 bytes per operand stage
#define STG (2 * ASTG)              // 36864 per stage (A+B)
#define SMEM_BAR (STAGES * STG)     // 110592: 6 mbarriers live here
#define SMEM_TOTAL (SMEM_BAR + 64)

// Scratch (device globals: no allocations).
__device__ __half g_Sh[(size_t)NN * NN];   // f16 logits, then probs in-place (32 MB)
__device__ __half g_Fh[(size_t)NN * NN];   // f16 feats (32 MB)

__device__ __forceinline__ uint32_t smem_u32(const void* p) {
    uint32_t a;
    asm("{ .reg .u64 t; cvta.to.shared.u64 t, %1; cvt.u32.u64 %0, t; }" : "=r"(a) : "l"(p));
    return a;
}

#define CP_ASYNC16(dst, src) \
    asm volatile("cp.async.cg.shared.global [%0], [%1], 16;" :: "r"(dst), "l"(src) : "memory")

#define MBAR_INIT(addr, cnt) \
    asm volatile("mbarrier.init.shared.b64 [%0], %1;" :: "r"(addr), "r"(cnt) : "memory")

#define MBAR_ARRIVE(addr) \
    asm volatile("mbarrier.arrive.shared.b64 _, [%0];" :: "r"(addr) : "memory")

// arrive (WITHOUT incrementing expected count) when ALL prior cp.async of this
// thread complete. The non-noinc variant nets to zero against a fixed init
// count and deadlocks -- that was the R9 bug.
#define CP_ASYNC_MBAR_ARRIVE(addr) \
    asm volatile("cp.async.mbarrier.arrive.noinc.shared.b64 [%0];" :: "r"(addr) : "memory")

#define MBAR_WAIT(addr, ph) do {                                                     \
    uint32_t _m = (addr), _p = (uint32_t)(ph), _d;                                   \
    asm volatile("{ .reg .pred p; mbarrier.try_wait.parity.shared.b64 p, [%1], %2;"  \
                 " selp.b32 %0, 1, 0, p; }" : "=r"(_d) : "r"(_m), "r"(_p) : "memory");\
    while (!_d) {                                                                    \
        asm volatile("{ .reg .pred p; mbarrier.try_wait.parity.shared.b64 p, [%1], %2, 0x989680;" \
                     " selp.b32 %0, 1, 0, p; }" : "=r"(_d) : "r"(_m), "r"(_p) : "memory");        \
    }                                                                                \
} while (0)

#define LDSM_X4(r0, r1, r2, r3, addr)                                        \
    asm volatile("ldmatrix.sync.aligned.m8n8.x4.shared.b16 {%0,%1,%2,%3}, [%4];" \
                 : "=r"(r0), "=r"(r1), "=r"(r2), "=r"(r3) : "r"(addr))

#define MMA_F16(d, a, b0, b1)                                                \
    asm volatile(                                                            \
        "mma.sync.aligned.m16n8k16.row.col.f32.f16.f16.f32 "                 \
        "{%0,%1,%2,%3}, {%4,%5,%6,%7}, {%8,%9}, {%0,%1,%2,%3};"              \
        : "+f"((d)[0]), "+f"((d)[1]), "+f"((d)[2]), "+f"((d)[3])             \
        : "r"((a)[0]), "r"((a)[1]), "r"((a)[2]), "r"((a)[3]),                \
          "r"(b0), "r"(b1))

// NT GEMM, f16 inputs, fp32 accum, OT output: C[i][j] = scale*sum_k A[i][k]*B[j][k]
// 8 warps, 64x32 warp tiles; mbarrier-decoupled 3-stage cp.async pipeline.
template <typename OT>
__global__ __launch_bounds__(THREADS, 2) void gemm_nt_f16(const __half* __restrict__ A,
                                                          const __half* __restrict__ B,
                                                          OT* __restrict__ C, float scale) {
    extern __shared__ char smem[];
    const uint32_t sb = smem_u32(smem);
    const int tid = threadIdx.x;
    const int wid = tid >> 5;
    const int lane = tid & 31;
    const int q = lane >> 2, r = lane & 3;
    const int wm = wid & 1;   // 2 warp rows x 64
    const int wn = wid >> 1;  // 4 warp cols x 32
    const int rowBase = blockIdx.y * BM;
    const int colBase = blockIdx.x * BN;

#define FULLB(s) (sb + SMEM_BAR + (s) * 8)
#define FREEB(s) (sb + SMEM_BAR + 24 + (s) * 8)

    if (tid == 0) {
#pragma unroll
        for (int s = 0; s < STAGES; s++) {
            MBAR_INIT(FULLB(s), THREADS);
            MBAR_INIT(FREEB(s), THREADS);
        }
    }
    __syncthreads();

    // cp.async: per operand tile 128 rows x 128B; thread t -> rows (t>>3)+{0,32,64,96}, chunk t&7
    const int ldRow = tid >> 3;
    const int ldC = (tid & 7) * 16;
    const char* Ag = (const char*)A + ((size_t)(rowBase + ldRow) * NN) * 2 + ldC;
    const char* Bg = (const char*)B + ((size_t)(colBase + ldRow) * NN) * 2 + ldC;
    const size_t GROW = (size_t)32 * NN * 2;

    // ldmatrix lane mapping
    const int ml = lane >> 3;
    const int lrow = (ml & 1) * 8 + (lane & 7);
    const int lk = (ml >> 1) * 16;
    const uint32_t aoff = (uint32_t)((wm * 64 + lrow) * LDB + lk);
    const uint32_t boff = (uint32_t)(ASTG + (wn * 32 + lrow) * LDB + lk);

    float c[4][4][4];
#pragma unroll
    for (int i = 0; i < 4; i++)
#pragma unroll
        for (int j = 0; j < 4; j++)
#pragma unroll
            for (int e = 0; e < 4; e++) c[i][j][e] = 0.f;

#define LOADSTAGE(sidx)                                                            \
    do {                                                                           \
        const uint32_t s_b = sb + (sidx) * STG;                                    \
        _Pragma("unroll") for (int l = 0; l < 4; l++) {                            \
            CP_ASYNC16(s_b + (ldRow + l * 32) * LDB + ldC, Ag + l * GROW);         \
            CP_ASYNC16(s_b + ASTG + (ldRow + l * 32) * LDB + ldC, Bg + l * GROW);  \
        }                                                                          \
        CP_ASYNC_MBAR_ARRIVE(FULLB(sidx));                                         \
        Ag += 128;                                                                 \
        Bg += 128;                                                                 \
    } while (0)

#define COMPUTE(sidx)                                                              \
    do {                                                                           \
        const uint32_t abase = sb + (sidx) * STG + aoff;                           \
        const uint32_t bbase = sb + (sidx) * STG + boff;                           \
        uint32_t a[2][4][4], b[2][2][4];                                           \
        _Pragma("unroll") for (int im = 0; im < 4; im++)                           \
            LDSM_X4(a[0][im][0], a[0][im][1], a[0][im][2], a[0][im][3],            \
                    abase + im * (16 * LDB));                                      \
        _Pragma("unroll") for (int jn = 0; jn < 2; jn++)                           \
            LDSM_X4(b[0][jn][0], b[0][jn][1], b[0][jn][2], b[0][jn][3],            \
                    bbase + jn * (16 * LDB));                                      \
        _Pragma("unroll") for (int ks = 0; ks < 4; ks++) {                         \
            const int cur = ks & 1;                                                \
            if (ks < 3) {                                                          \
                _Pragma("unroll") for (int im = 0; im < 4; im++)                   \
                    LDSM_X4(a[cur ^ 1][im][0], a[cur ^ 1][im][1],                  \
                            a[cur ^ 1][im][2], a[cur ^ 1][im][3],                  \
                            abase + im * (16 * LDB) + (ks + 1) * 32);              \
                _Pragma("unroll") for (int jn = 0; jn < 2; jn++)                   \
                    LDSM_X4(b[cur ^ 1][jn][0], b[cur ^ 1][jn][1],                  \
                            b[cur ^ 1][jn][2], b[cur ^ 1][jn][3],                  \
                            bbase + jn * (16 * LDB) + (ks + 1) * 32);              \
            }                                                                      \
            _Pragma("unroll") for (int im = 0; im < 4; im++)                       \
                _Pragma("unroll") for (int in_ = 0; in_ < 4; in_++) {              \
                    const int jn = in_ >> 1, o = in_ & 1;                          \
                    MMA_F16(c[im][in_], a[cur][im], b[cur][jn][o], b[cur][jn][2 + o]); \
                }                                                                  \
        }                                                                          \
    } while (0)

    // prologue: fill stages 0 and 1 (k-tiles 0, 1)
    LOADSTAGE(0);
    LOADSTAGE(1);

    // main loop unrolled by 3; kt = 3g + i, stage = kt % 3.
    // per iter: wait full -> compute -> arrive free -> (wait free of stage kt+2 -> load kt+2)
    int pg = 0;  // g & 1
    for (int g = 0; g < 21; g++) {
        // i = 0: kt = 3g, compute stage 0; load kt+2 = 3g+2 -> stage 2
        MBAR_WAIT(FULLB(0), pg);
        COMPUTE(0);
        MBAR_ARRIVE(FREEB(0));
        if (g > 0) MBAR_WAIT(FREEB(2), pg ^ 1);  // stage 2 consumed at idx g-1
        LOADSTAGE(2);
        // i = 1: kt = 3g+1, compute stage 1; load 3g+3 -> stage 0 (freed at 3g, idx g)
        MBAR_WAIT(FULLB(1), pg);
        COMPUTE(1);
        MBAR_ARRIVE(FREEB(1));
        MBAR_WAIT(FREEB(0), pg);
        LOADSTAGE(0);
        // i = 2: kt = 3g+2, compute stage 2; load 3g+4 -> stage 1 (freed at 3g+1, idx g)
        MBAR_WAIT(FULLB(2), pg);
        COMPUTE(2);
        MBAR_ARRIVE(FREEB(2));
        if (g < 20) {
            MBAR_WAIT(FREEB(1), pg);
            LOADSTAGE(1);
        }
        pg ^= 1;
    }
    // tail: kt = 63, stage 0, fill idx 21 -> parity 1 == pg
    MBAR_WAIT(FULLB(0), pg);
    COMPUTE(0);

    // epilogue
#pragma unroll
    for (int im = 0; im < 4; im++) {
        const int row0 = rowBase + wm * 64 + im * 16 + q;
#pragma unroll
        for (int in_ = 0; in_ < 4; in_++) {
            const int col = colBase + wn * 32 + in_ * 8 + 2 * r;
            if constexpr (sizeof(OT) == 4) {
                float2 v0 = make_float2(c[im][in_][0] * scale, c[im][in_][1] * scale);
                float2 v1 = make_float2(c[im][in_][2] * scale, c[im][in_][3] * scale);
                *reinterpret_cast<float2*>((float*)C + (size_t)row0 * NN + col) = v0;
                *reinterpret_cast<float2*>((float*)C + (size_t)(row0 + 8) * NN + col) = v1;
            } else {
                __half2 h0 = __floats2half2_rn(c[im][in_][0] * scale, c[im][in_][1] * scale);
                __half2 h1 = __floats2half2_rn(c[im][in_][2] * scale, c[im][in_][3] * scale);
                *reinterpret_cast<__half2*>((__half*)C + (size_t)row0 * NN + col) = h0;
                *reinterpret_cast<__half2*>((__half*)C + (size_t)(row0 + 8) * NN + col) = h1;
            }
        }
    }
}

// ---------------- prep: feats f32 -> f16 ----------------
__global__ __launch_bounds__(256) void prep_feats(const float* __restrict__ in,
                                                  __half* __restrict__ out) {
    size_t i = ((size_t)blockIdx.x * 256 + threadIdx.x) * 8;
    float4 v0 = *reinterpret_cast<const float4*>(in + i);
    float4 v1 = *reinterpret_cast<const float4*>(in + i + 4);
    __half2 h[4];
    h[0] = __floats2half2_rn(v0.x, v0.y);
    h[1] = __floats2half2_rn(v0.z, v0.w);
    h[2] = __floats2half2_rn(v1.x, v1.y);
    h[3] = __floats2half2_rn(v1.z, v1.w);
    *reinterpret_cast<uint4*>(out + i) = *reinterpret_cast<uint4*>(h);
}

// ---------------- row softmax on f16 logits, diag masked, f16 probs in-place ----------------
__global__ __launch_bounds__(256) void softmax_rows(__half* __restrict__ S) {
    __shared__ float row[NN];  // 16 KB
    __shared__ float red[256];
    const int ri = blockIdx.x;
    const int t = threadIdx.x;
    __half2* rp = reinterpret_cast<__half2*>(S + (size_t)ri * NN);

    for (int j = t; j < NN / 2; j += 256) {
        float2 v = __half22float2(rp[j]);
        row[2 * j] = v.x;
        row[2 * j + 1] = v.y;
    }
    __syncthreads();
    if (t == 0) row[ri] = -3.4e38f;  // mask diagonal
    __syncthreads();

    float m = -3.4e38f;
    for (int j = t; j < NN; j += 256) m = fmaxf(m, row[j]);
    red[t] = m;
    __syncthreads();
    for (int s = 128; s > 0; s >>= 1) {
        if (t < s) red[t] = fmaxf(red[t], red[t + s]);
        __syncthreads();
    }
    m = red[0];
    __syncthreads();

    float sum = 0.f;
    for (int j = t; j < NN; j += 256) {
        float e = __expf(row[j] - m);
        row[j] = e;
        sum += e;
    }
    red[t] = sum;
    __syncthreads();
    for (int s = 128; s > 0; s >>= 1) {
        if (t < s) red[t] += red[t + s];
        __syncthreads();
    }
    const float inv = 1.f / red[0];
    __syncthreads();

    for (int j = t; j < NN / 2; j += 256)
        rp[j] = __floats2half2_rn(row[2 * j] * inv, row[2 * j + 1] * inv);
}

extern "C" void kernel_launch(void* const* d_in, const int* in_sizes, int n_in,
                              void* d_out, int out_size) {
    const float* feats = (const float*)d_in[0];
    float* out = (float*)d_out;

    void *sp, *fp;
    cudaGetSymbolAddress(&sp, g_Sh);
    cudaGetSymbolAddress(&fp, g_Fh);
    __half* Sh = (__half*)sp;
    __half* Fh = (__half*)fp;

    cudaFuncSetAttribute(gemm_nt_f16<__half>, cudaFuncAttributeMaxDynamicSharedMemorySize,
                         SMEM_TOTAL);
    cudaFuncSetAttribute(gemm_nt_f16<float>, cudaFuncAttributeMaxDynamicSharedMemorySize,
                         SMEM_TOTAL);

    prep_feats<<<(NN * NN) / 2048, 256>>>(feats, Fh);

    dim3 grid(NN / BN, NN / BM);  // (32, 32)
    // S = Fh @ Fh^T / D  (f16 logits out)
    gemm_nt_f16<__half><<<grid, THREADS, SMEM_TOTAL>>>(Fh, Fh, Sh, 1.0f / (float)NN);
    // P = softmax(S), diag masked, in-place f16
    softmax_rows<<<NN, 256>>>(Sh);
    // out = P @ Fh^T / sqrt(D)  (fp32 out)
    gemm_nt_f16<float><<<grid, THREADS, SMEM_TOTAL>>>(Sh, Fh, out, 1.0f / 64.0f);
}